// round 6
// baseline (speedup 1.0000x reference)
#include <cuda_runtime.h>
#include <math.h>
#include <float.h>

#define G 32
#define GC (G * G * G)
#define NPC 8192   // points per (cloud, batch)
#define NB 4       // batches
#define NCB 8      // cloud*NB + b slots

// Static scratch (no cudaMalloc allowed anywhere).
__device__ unsigned g_bkey[6];            // bbox keys: min x,y,z ; max x,y,z
__device__ int g_cnt[NCB][GC];
__device__ int g_start[NCB][GC + 1];
__device__ int g_cid[NCB][NPC];
__device__ int g_rnk[NCB][NPC];
__device__ int g_oidx[NCB][NPC];
__device__ float4 g_pts[NCB][NPC];        // sorted (x, y, z, |p|^2/2)
__device__ float g_min0[NB * NPC];        // per point of cloud2: NN distance
__device__ float g_min1[NB * NPC];        // per point of cloud1: NN distance
__device__ float g_part[128];

// Monotone float<->uint map (works for negatives) for atomic min/max.
__device__ __forceinline__ unsigned fkey(float f) {
    unsigned u = __float_as_uint(f);
    return (u & 0x80000000u) ? ~u : (u | 0x80000000u);
}
__device__ __forceinline__ float fdec(unsigned k) {
    return (k & 0x80000000u) ? __uint_as_float(k & 0x7FFFFFFFu) : __uint_as_float(~k);
}

__device__ __forceinline__ void load_grid(float& mnx, float& mny, float& mnz,
                                          float& inv, float& h) {
    mnx = fdec(g_bkey[0]);
    mny = fdec(g_bkey[1]);
    mnz = fdec(g_bkey[2]);
    float ex = fdec(g_bkey[3]) - mnx;
    float ey = fdec(g_bkey[4]) - mny;
    float ez = fdec(g_bkey[5]) - mnz;
    float ext = fmaxf(ex, fmaxf(ey, ez)) * (1.f + 1e-5f) + 1e-20f;
    h = ext / (float)G;
    inv = (float)G / ext;
}
__device__ __forceinline__ int cellof(float x, float mn, float inv) {
    int c = (int)((x - mn) * inv);
    return min(G - 1, max(0, c));
}

__global__ void zero_kernel() {
    int i = blockIdx.x * blockDim.x + threadIdx.x;
    for (int j = i; j < NCB * GC; j += gridDim.x * blockDim.x) ((int*)g_cnt)[j] = 0;
    if (i < 3) g_bkey[i] = 0xFFFFFFFFu;
    if (i >= 3 && i < 6) g_bkey[i] = 0u;
}

__global__ void bbox_kernel(const float* __restrict__ A, const float* __restrict__ C,
                            int nA, int nC) {
    int i = blockIdx.x * blockDim.x + threadIdx.x;
    int stride = gridDim.x * blockDim.x;
    float mn[3] = {FLT_MAX, FLT_MAX, FLT_MAX};
    float mx[3] = {-FLT_MAX, -FLT_MAX, -FLT_MAX};
    for (int j = i; j < nA + nC; j += stride) {
        const float* p = (j < nA) ? (A + (size_t)j * 3) : (C + (size_t)(j - nA) * 3);
#pragma unroll
        for (int a = 0; a < 3; a++) {
            float v = p[a];
            mn[a] = fminf(mn[a], v);
            mx[a] = fmaxf(mx[a], v);
        }
    }
#pragma unroll
    for (int off = 16; off > 0; off >>= 1) {
#pragma unroll
        for (int a = 0; a < 3; a++) {
            mn[a] = fminf(mn[a], __shfl_xor_sync(0xFFFFFFFFu, mn[a], off));
            mx[a] = fmaxf(mx[a], __shfl_xor_sync(0xFFFFFFFFu, mx[a], off));
        }
    }
    if ((threadIdx.x & 31) == 0) {
#pragma unroll
        for (int a = 0; a < 3; a++) {
            atomicMin(&g_bkey[a], fkey(mn[a]));
            atomicMax(&g_bkey[3 + a], fkey(mx[a]));
        }
    }
}

__global__ void count_kernel(const float* __restrict__ P, int cloud, int n) {
    int i = blockIdx.x * blockDim.x + threadIdx.x;
    if (i >= NB * n) return;
    int b = i / n, slot = i % n;
    float mnx, mny, mnz, inv, h;
    load_grid(mnx, mny, mnz, inv, h);
    const float* p = P + (size_t)i * 3;
    int cx = cellof(p[0], mnx, inv);
    int cy = cellof(p[1], mny, inv);
    int cz = cellof(p[2], mnz, inv);
    int cid = (cz * G + cy) * G + cx;
    int cb = cloud * NB + b;
    g_cid[cb][slot] = cid;
    g_rnk[cb][slot] = atomicAdd(&g_cnt[cb][cid], 1);
}

__global__ void scan_kernel() {
    const int cb = blockIdx.x;
    const int t = threadIdx.x;
    const int per = GC / 1024;  // 32 cells per thread
    const int base = t * per;
    int s = 0;
    for (int i = 0; i < per; i++) s += g_cnt[cb][base + i];
    __shared__ int sh[1024];
    sh[t] = s;
    __syncthreads();
    for (int off = 1; off < 1024; off <<= 1) {
        int v = (t >= off) ? sh[t - off] : 0;
        __syncthreads();
        sh[t] += v;
        __syncthreads();
    }
    int excl = (t == 0) ? 0 : sh[t - 1];
    for (int i = 0; i < per; i++) {
        g_start[cb][base + i] = excl;
        excl += g_cnt[cb][base + i];
    }
    if (t == 1023) g_start[cb][GC] = sh[1023];
}

__global__ void scatter_kernel(const float* __restrict__ P, int cloud, int n) {
    int i = blockIdx.x * blockDim.x + threadIdx.x;
    if (i >= NB * n) return;
    int b = i / n, slot = i % n, cb = cloud * NB + b;
    const float* p = P + (size_t)i * 3;
    float x = p[0], y = p[1], z = p[2];
    int pos = g_start[cb][g_cid[cb][slot]] + g_rnk[cb][slot];
    g_pts[cb][pos] = make_float4(x, y, z, 0.5f * (x * x + y * y + z * z));
    g_oidx[cb][pos] = slot;
}

// Exact NN search with expanding Chebyshev rings.
// t = h_p - q.p accumulated per candidate; d^2 = 2*(t_min + g_q).
#define SCAN_CELL(CID)                                                              \
    {                                                                               \
        int s_ = cs[CID], e_ = cs[(CID) + 1];                                       \
        for (int k_ = s_; k_ < e_; k_++) {                                          \
            float4 p_ = pts[k_];                                                    \
            float t_ = fmaf(p_.x, nqx, fmaf(p_.y, nqy, fmaf(p_.z, nqz, p_.w)));     \
            tmin = fminf(tmin, t_);                                                 \
        }                                                                           \
    }

__global__ void search_kernel(int qcloud, int rcloud, int which, int qn) {
    int i = blockIdx.x * blockDim.x + threadIdx.x;
    if (i >= NB * qn) return;
    int b = i / qn, slot = i % qn;
    int qcb = qcloud * NB + b, rcb = rcloud * NB + b;
    float mnx, mny, mnz, inv, h;
    load_grid(mnx, mny, mnz, inv, h);

    float4 q = g_pts[qcb][slot];  // cell-sorted queries -> warp-coherent rings
    float nqx = -q.x, nqy = -q.y, nqz = -q.z;
    const float gq = q.w;
    int cx = cellof(q.x, mnx, inv);
    int cy = cellof(q.y, mny, inv);
    int cz = cellof(q.z, mnz, inv);

    const float4* __restrict__ pts = g_pts[rcb];
    const int* __restrict__ cs = g_start[rcb];

    float tmin = FLT_MAX;
    float best = FLT_MAX;
    int R = 0;
    while (true) {
        int z0 = max(cz - R, 0), z1 = min(cz + R, G - 1);
        int y0 = max(cy - R, 0), y1 = min(cy + R, G - 1);
        int x0 = max(cx - R, 0), x1 = min(cx + R, G - 1);
        for (int z = z0; z <= z1; z++) {
            int adz = z - cz;
            adz = adz < 0 ? -adz : adz;
            for (int y = y0; y <= y1; y++) {
                int ady = y - cy;
                ady = ady < 0 ? -ady : ady;
                if (adz > ady) ady = adz;
                int rowb = (z * G + y) * G;
                if (ady == R) {
                    for (int x = x0; x <= x1; x++) SCAN_CELL(rowb + x);
                } else {
                    if (cx - R >= 0) SCAN_CELL(rowb + cx - R);
                    if (cx + R <= G - 1) SCAN_CELL(rowb + cx + R);
                }
            }
        }
        best = fmaxf(0.f, 2.f * (tmin + gq));
        float bd = (float)R * h;  // unscanned points are >= R*h away
        if (best <= bd * bd || R >= G) break;
        R++;
    }
    float* out = which ? g_min1 : g_min0;
    out[(size_t)b * qn + g_oidx[qcb][slot]] = sqrtf(best);
}

// ---------- two-stage deterministic reduction (arrays hold d already) ----------
__global__ void reduce1_kernel(int len0, int len1, float inv0, float inv1) {
    const int bid = blockIdx.x;  // 0..63 -> g_min0, 64..127 -> g_min1
    const bool first = bid < 64;
    const float* src = first ? g_min0 : g_min1;
    const int len = first ? len0 : len1;
    const float inv = first ? inv0 : inv1;
    const int lb = first ? bid : bid - 64;
    const int slice = (len + 63) / 64;
    const int start = lb * slice;
    int end = start + slice;
    if (end > len) end = len;

    float acc = 0.f;
    for (int i = start + threadIdx.x; i < end; i += 256) acc += src[i] * inv;

#pragma unroll
    for (int off = 16; off > 0; off >>= 1)
        acc += __shfl_down_sync(0xFFFFFFFFu, acc, off);

    __shared__ float s[8];
    if ((threadIdx.x & 31) == 0) s[threadIdx.x >> 5] = acc;
    __syncthreads();
    if (threadIdx.x < 8) {
        float v = s[threadIdx.x];
#pragma unroll
        for (int off = 4; off > 0; off >>= 1)
            v += __shfl_down_sync(0xFFu, v, off);
        if (threadIdx.x == 0) g_part[bid] = v;
    }
}

__global__ void reduce2_kernel(float* __restrict__ out) {
    __shared__ float s[128];
    s[threadIdx.x] = g_part[threadIdx.x];
    __syncthreads();
    for (int st = 64; st > 0; st >>= 1) {
        if (threadIdx.x < st) s[threadIdx.x] += s[threadIdx.x + st];
        __syncthreads();
    }
    if (threadIdx.x == 0) out[0] = s[0];
}

extern "C" void kernel_launch(void* const* d_in, const int* in_sizes, int n_in,
                              void* d_out, int out_size) {
    const float* in1 = (const float*)d_in[0];  // [B, N, 3] cloud1
    const float* in2 = (const float*)d_in[1];  // [B, M, 3] cloud2
    const int K = 3;
    const int N = in_sizes[0] / (NB * K);
    const int M = in_sizes[1] / (NB * K);

    zero_kernel<<<512, 512>>>();
    bbox_kernel<<<128, 256>>>(in1, in2, NB * N, NB * M);

    const int bc1 = (NB * N + 255) / 256;
    const int bc2 = (NB * M + 255) / 256;
    count_kernel<<<bc1, 256>>>(in1, 0, N);
    count_kernel<<<bc2, 256>>>(in2, 1, M);
    scan_kernel<<<NCB, 1024>>>();
    scatter_kernel<<<bc1, 256>>>(in1, 0, N);
    scatter_kernel<<<bc2, 256>>>(in2, 1, M);

    // dist1: each point of cloud1 vs grid of cloud2
    search_kernel<<<bc1, 256>>>(0, 1, /*which=*/1, N);
    // dist0: each point of cloud2 vs grid of cloud1
    search_kernel<<<bc2, 256>>>(1, 0, /*which=*/0, M);

    reduce1_kernel<<<128, 256>>>(NB * M, NB * N, 1.f / (float)(NB * M), 1.f / (float)(NB * N));
    reduce2_kernel<<<1, 128>>>((float*)d_out);
}

// round 7
// speedup vs baseline: 3.5371x; 3.5371x over previous
#include <cuda_runtime.h>
#include <math.h>
#include <float.h>

#define G 16
#define GC (G * G * G)
#define NPC 8192   // max points per (cloud, batch)
#define NB 4       // batches
#define NCB 8      // cloud*NB + b slots

// Static scratch (no cudaMalloc).
__device__ unsigned g_bkey[6] = {0xFFFFFFFFu, 0xFFFFFFFFu, 0xFFFFFFFFu, 0u, 0u, 0u};
__device__ int g_cnt[NCB][GC];
__device__ int g_start[NCB][GC + 1];
__device__ int g_cid[NCB][NPC];
__device__ int g_rnk[NCB][NPC];
__device__ int g_oidx[NCB][NPC];
__device__ float4 g_pts[NCB][NPC];  // cell-sorted (x, y, z, |p|^2/2)
__device__ float g_min0[NB * NPC];  // per point of cloud2: NN distance
__device__ float g_min1[NB * NPC];  // per point of cloud1: NN distance
__device__ float g_part[128];

// Monotone float<->uint map for atomic min/max (handles negatives).
__device__ __forceinline__ unsigned fkey(float f) {
    unsigned u = __float_as_uint(f);
    return (u & 0x80000000u) ? ~u : (u | 0x80000000u);
}
__device__ __forceinline__ float fdec(unsigned k) {
    return (k & 0x80000000u) ? __uint_as_float(k & 0x7FFFFFFFu) : __uint_as_float(~k);
}

__device__ __forceinline__ void load_grid(float& mnx, float& mny, float& mnz,
                                          float& inv, float& h) {
    mnx = fdec(g_bkey[0]);
    mny = fdec(g_bkey[1]);
    mnz = fdec(g_bkey[2]);
    float ex = fdec(g_bkey[3]) - mnx;
    float ey = fdec(g_bkey[4]) - mny;
    float ez = fdec(g_bkey[5]) - mnz;
    float ext = fmaxf(ex, fmaxf(ey, ez)) * (1.f + 1e-5f) + 1e-20f;
    h = ext / (float)G;
    inv = (float)G / ext;
}
__device__ __forceinline__ int cellof(float x, float mn, float inv) {
    int c = (int)((x - mn) * inv);
    return min(G - 1, max(0, c));
}

// ---------- bbox (+ zero g_cnt; bkey atomics are replay-idempotent) ----------
__global__ void bbox_kernel(const float* __restrict__ A, const float* __restrict__ C,
                            int nA, int nC) {
    int i = blockIdx.x * blockDim.x + threadIdx.x;
    int stride = gridDim.x * blockDim.x;
    for (int j = i; j < NCB * GC; j += stride) ((int*)g_cnt)[j] = 0;

    float mn[3] = {FLT_MAX, FLT_MAX, FLT_MAX};
    float mx[3] = {-FLT_MAX, -FLT_MAX, -FLT_MAX};
    for (int j = i; j < nA + nC; j += stride) {
        const float* p = (j < nA) ? (A + (size_t)j * 3) : (C + (size_t)(j - nA) * 3);
#pragma unroll
        for (int a = 0; a < 3; a++) {
            float v = p[a];
            mn[a] = fminf(mn[a], v);
            mx[a] = fmaxf(mx[a], v);
        }
    }
#pragma unroll
    for (int off = 16; off > 0; off >>= 1) {
#pragma unroll
        for (int a = 0; a < 3; a++) {
            mn[a] = fminf(mn[a], __shfl_xor_sync(0xFFFFFFFFu, mn[a], off));
            mx[a] = fmaxf(mx[a], __shfl_xor_sync(0xFFFFFFFFu, mx[a], off));
        }
    }
    if ((threadIdx.x & 31) == 0) {
#pragma unroll
        for (int a = 0; a < 3; a++) {
            atomicMin(&g_bkey[a], fkey(mn[a]));
            atomicMax(&g_bkey[3 + a], fkey(mx[a]));
        }
    }
}

// ---------- count (both clouds in one launch) ----------
__global__ void count_kernel(const float* __restrict__ P1, const float* __restrict__ P2,
                             int N, int M) {
    int i = blockIdx.x * blockDim.x + threadIdx.x;
    const int tot1 = NB * N;
    if (i >= tot1 + NB * M) return;
    float mnx, mny, mnz, inv, h;
    load_grid(mnx, mny, mnz, inv, h);
    int cloud, b, slot, n;
    const float* P;
    if (i < tot1) { cloud = 0; n = N; b = i / N; slot = i % N; P = P1 + (size_t)i * 3; }
    else { cloud = 1; n = M; int j = i - tot1; b = j / M; slot = j % M; P = P2 + (size_t)j * 3; }
    (void)n;
    int cx = cellof(P[0], mnx, inv);
    int cy = cellof(P[1], mny, inv);
    int cz = cellof(P[2], mnz, inv);
    int cid = (cz * G + cy) * G + cx;
    int cb = cloud * NB + b;
    g_cid[cb][slot] = cid;
    g_rnk[cb][slot] = atomicAdd(&g_cnt[cb][cid], 1);
}

// ---------- exclusive scan per (cloud,batch): GC=4096 cells, 1024 threads ----------
__global__ void scan_kernel() {
    const int cb = blockIdx.x;
    const int t = threadIdx.x;
    const int per = GC / 1024;  // 4
    const int base = t * per;
    int s = 0;
#pragma unroll
    for (int i = 0; i < per; i++) s += g_cnt[cb][base + i];
    __shared__ int sh[1024];
    sh[t] = s;
    __syncthreads();
    for (int off = 1; off < 1024; off <<= 1) {
        int v = (t >= off) ? sh[t - off] : 0;
        __syncthreads();
        sh[t] += v;
        __syncthreads();
    }
    int excl = (t == 0) ? 0 : sh[t - 1];
#pragma unroll
    for (int i = 0; i < per; i++) {
        g_start[cb][base + i] = excl;
        excl += g_cnt[cb][base + i];
    }
    if (t == 1023) g_start[cb][GC] = sh[1023];
}

// ---------- scatter (both clouds) ----------
__global__ void scatter_kernel(const float* __restrict__ P1, const float* __restrict__ P2,
                               int N, int M) {
    int i = blockIdx.x * blockDim.x + threadIdx.x;
    const int tot1 = NB * N;
    if (i >= tot1 + NB * M) return;
    int cb, slot;
    const float* p;
    if (i < tot1) { cb = 0 * NB + i / N; slot = i % N; p = P1 + (size_t)i * 3; }
    else { int j = i - tot1; cb = 1 * NB + j / M; slot = j % M; p = P2 + (size_t)j * 3; }
    float x = p[0], y = p[1], z = p[2];
    int pos = g_start[cb][g_cid[cb][slot]] + g_rnk[cb][slot];
    g_pts[cb][pos] = make_float4(x, y, z, 0.5f * (x * x + y * y + z * z));
    g_oidx[cb][pos] = slot;
}

// ---------- warp-per-query exact NN search, both directions in one launch ----------
// t = h_p - q.p per candidate; d^2 = 2*(tmin + g_q). Unscanned points >= R*h away.
__global__ __launch_bounds__(256) void search_kernel(int N, int M) {
    const int gw = (blockIdx.x * blockDim.x + threadIdx.x) >> 5;
    const int lane = threadIdx.x & 31;
    const int tot1 = NB * N;
    if (gw >= tot1 + NB * M) return;

    int qcb, rcb, qn, b, slot, which;
    if (gw < tot1) { b = gw / N; slot = gw % N; qcb = b; rcb = NB + b; qn = N; which = 1; }
    else { int j = gw - tot1; b = j / M; slot = j % M; qcb = NB + b; rcb = b; qn = M; which = 0; }

    float mnx, mny, mnz, inv, h;
    load_grid(mnx, mny, mnz, inv, h);

    const float4 q = g_pts[qcb][slot];  // broadcast load (warp-uniform)
    const float nqx = -q.x, nqy = -q.y, nqz = -q.z, gq = q.w;
    const int cx = cellof(q.x, mnx, inv);
    const int cy = cellof(q.y, mny, inv);
    const int cz = cellof(q.z, mnz, inv);

    const float4* __restrict__ pts = g_pts[rcb];
    const int* __restrict__ cs = g_start[rcb];

    float tmin = FLT_MAX;
    float best;
    int R = 1;
    for (;; R++) {
        // Scan the full (2R+1)^3 box (idempotent rescans on ring growth are rare).
        const int side = 2 * R + 1;
        const int ncell = side * side * side;
        for (int base = 0; base < ncell; base += 32) {
            const int ci = base + lane;
            int st = 0, cnt = 0;
            if (ci < ncell) {
                int dz = ci / (side * side);
                int rem = ci - dz * side * side;
                int dy = rem / side;
                int dx = rem - dy * side;
                int z = cz - R + dz, y = cy - R + dy, x = cx - R + dx;
                if (((unsigned)z < G) && ((unsigned)y < G) && ((unsigned)x < G)) {
                    int cid = (z * G + y) * G + x;
                    st = cs[cid];
                    cnt = cs[cid + 1] - st;
                }
            }
            unsigned mask = __ballot_sync(0xFFFFFFFFu, cnt > 0);
            while (mask) {
                const int c = __ffs(mask) - 1;
                mask &= mask - 1;
                const int s = __shfl_sync(0xFFFFFFFFu, st, c);
                const int n = __shfl_sync(0xFFFFFFFFu, cnt, c);
                for (int k = lane; k < n; k += 32) {
                    float4 p = pts[s + k];
                    float t = fmaf(p.x, nqx, fmaf(p.y, nqy, fmaf(p.z, nqz, p.w)));
                    tmin = fminf(tmin, t);
                }
            }
        }
        // Warp-reduce tmin (xor so all lanes agree).
        float tm = tmin;
#pragma unroll
        for (int off = 16; off > 0; off >>= 1)
            tm = fminf(tm, __shfl_xor_sync(0xFFFFFFFFu, tm, off));
        best = fmaxf(0.f, 2.f * (tm + gq));
        const float bd = (float)R * h;
        if (best <= bd * bd || R >= G) break;
    }

    if (lane == 0) {
        float* out = which ? g_min1 : g_min0;
        out[(size_t)b * qn + g_oidx[qcb][slot]] = sqrtf(best);
    }
}

// ---------- two-stage deterministic reduction ----------
__global__ void reduce1_kernel(int len0, int len1, float inv0, float inv1) {
    const int bid = blockIdx.x;
    const bool first = bid < 64;
    const float* src = first ? g_min0 : g_min1;
    const int len = first ? len0 : len1;
    const float inv = first ? inv0 : inv1;
    const int lb = first ? bid : bid - 64;
    const int slice = (len + 63) / 64;
    const int start = lb * slice;
    int end = start + slice;
    if (end > len) end = len;

    float acc = 0.f;
    for (int i = start + threadIdx.x; i < end; i += 256) acc += src[i] * inv;
#pragma unroll
    for (int off = 16; off > 0; off >>= 1)
        acc += __shfl_down_sync(0xFFFFFFFFu, acc, off);
    __shared__ float s[8];
    if ((threadIdx.x & 31) == 0) s[threadIdx.x >> 5] = acc;
    __syncthreads();
    if (threadIdx.x < 8) {
        float v = s[threadIdx.x];
#pragma unroll
        for (int off = 4; off > 0; off >>= 1)
            v += __shfl_down_sync(0xFFu, v, off);
        if (threadIdx.x == 0) g_part[bid] = v;
    }
}

__global__ void reduce2_kernel(float* __restrict__ out) {
    __shared__ float s[128];
    s[threadIdx.x] = g_part[threadIdx.x];
    __syncthreads();
    for (int st = 64; st > 0; st >>= 1) {
        if (threadIdx.x < st) s[threadIdx.x] += s[threadIdx.x + st];
        __syncthreads();
    }
    if (threadIdx.x == 0) out[0] = s[0];
}

extern "C" void kernel_launch(void* const* d_in, const int* in_sizes, int n_in,
                              void* d_out, int out_size) {
    const float* in1 = (const float*)d_in[0];  // [B, N, 3] cloud1
    const float* in2 = (const float*)d_in[1];  // [B, M, 3] cloud2
    const int K = 3;
    const int N = in_sizes[0] / (NB * K);
    const int M = in_sizes[1] / (NB * K);
    const int totPts = NB * (N + M);

    bbox_kernel<<<128, 256>>>(in1, in2, NB * N, NB * M);
    count_kernel<<<(totPts + 255) / 256, 256>>>(in1, in2, N, M);
    scan_kernel<<<NCB, 1024>>>();
    scatter_kernel<<<(totPts + 255) / 256, 256>>>(in1, in2, N, M);
    search_kernel<<<(totPts * 32 + 255) / 256, 256>>>(N, M);
    reduce1_kernel<<<128, 256>>>(NB * M, NB * N, 1.f / (float)(NB * M), 1.f / (float)(NB * N));
    reduce2_kernel<<<1, 128>>>((float*)d_out);
}

// round 8
// speedup vs baseline: 6.8625x; 1.9401x over previous
#include <cuda_runtime.h>
#include <math.h>
#include <float.h>

#define G 16
#define GC (G * G * G)
#define NPC 8192   // max points per (cloud, batch)
#define NB 4       // batches
#define NCB 8      // cloud*NB + b slots

// Static scratch (no cudaMalloc).
__device__ unsigned g_bkey[6] = {0xFFFFFFFFu, 0xFFFFFFFFu, 0xFFFFFFFFu, 0u, 0u, 0u};
__device__ int g_cnt[NCB][GC];
__device__ int g_start[NCB][GC + 1];
__device__ int g_cid[NCB][NPC];
__device__ int g_rnk[NCB][NPC];
__device__ float4 g_pts[NCB][NPC];  // cell-sorted (x, y, z, |p|^2/2)
__device__ float g_part[256];

// Monotone float<->uint map for atomic min/max (handles negatives).
__device__ __forceinline__ unsigned fkey(float f) {
    unsigned u = __float_as_uint(f);
    return (u & 0x80000000u) ? ~u : (u | 0x80000000u);
}
__device__ __forceinline__ float fdec(unsigned k) {
    return (k & 0x80000000u) ? __uint_as_float(k & 0x7FFFFFFFu) : __uint_as_float(~k);
}

__device__ __forceinline__ void load_grid(float& mnx, float& mny, float& mnz,
                                          float& inv, float& h) {
    mnx = fdec(g_bkey[0]);
    mny = fdec(g_bkey[1]);
    mnz = fdec(g_bkey[2]);
    float ex = fdec(g_bkey[3]) - mnx;
    float ey = fdec(g_bkey[4]) - mny;
    float ez = fdec(g_bkey[5]) - mnz;
    float ext = fmaxf(ex, fmaxf(ey, ez)) * (1.f + 1e-5f) + 1e-20f;
    h = ext / (float)G;
    inv = (float)G / ext;
}
__device__ __forceinline__ int cellof(float x, float mn, float inv) {
    int c = (int)((x - mn) * inv);
    return min(G - 1, max(0, c));
}

// ---------- bbox (+ zero g_cnt; bkey atomics are replay-idempotent) ----------
__global__ void bbox_kernel(const float* __restrict__ A, const float* __restrict__ C,
                            int nA, int nC) {
    int i = blockIdx.x * blockDim.x + threadIdx.x;
    int stride = gridDim.x * blockDim.x;
    for (int j = i; j < NCB * GC; j += stride) ((int*)g_cnt)[j] = 0;

    float mn[3] = {FLT_MAX, FLT_MAX, FLT_MAX};
    float mx[3] = {-FLT_MAX, -FLT_MAX, -FLT_MAX};
    for (int j = i; j < nA + nC; j += stride) {
        const float* p = (j < nA) ? (A + (size_t)j * 3) : (C + (size_t)(j - nA) * 3);
#pragma unroll
        for (int a = 0; a < 3; a++) {
            float v = p[a];
            mn[a] = fminf(mn[a], v);
            mx[a] = fmaxf(mx[a], v);
        }
    }
#pragma unroll
    for (int off = 16; off > 0; off >>= 1) {
#pragma unroll
        for (int a = 0; a < 3; a++) {
            mn[a] = fminf(mn[a], __shfl_xor_sync(0xFFFFFFFFu, mn[a], off));
            mx[a] = fmaxf(mx[a], __shfl_xor_sync(0xFFFFFFFFu, mx[a], off));
        }
    }
    if ((threadIdx.x & 31) == 0) {
#pragma unroll
        for (int a = 0; a < 3; a++) {
            atomicMin(&g_bkey[a], fkey(mn[a]));
            atomicMax(&g_bkey[3 + a], fkey(mx[a]));
        }
    }
}

// ---------- count (both clouds in one launch) ----------
__global__ void count_kernel(const float* __restrict__ P1, const float* __restrict__ P2,
                             int N, int M) {
    int i = blockIdx.x * blockDim.x + threadIdx.x;
    const int tot1 = NB * N;
    if (i >= tot1 + NB * M) return;
    float mnx, mny, mnz, inv, h;
    load_grid(mnx, mny, mnz, inv, h);
    int cb, slot;
    const float* P;
    if (i < tot1) { cb = i / N; slot = i % N; P = P1 + (size_t)i * 3; }
    else { int j = i - tot1; cb = NB + j / M; slot = j % M; P = P2 + (size_t)j * 3; }
    int cx = cellof(P[0], mnx, inv);
    int cy = cellof(P[1], mny, inv);
    int cz = cellof(P[2], mnz, inv);
    int cid = (cz * G + cy) * G + cx;
    g_cid[cb][slot] = cid;
    g_rnk[cb][slot] = atomicAdd(&g_cnt[cb][cid], 1);
}

// ---------- exclusive scan per (cloud,batch): GC=4096 cells, 1024 threads ----------
__global__ void scan_kernel() {
    const int cb = blockIdx.x;
    const int t = threadIdx.x;
    const int per = GC / 1024;  // 4
    const int base = t * per;
    int s = 0;
#pragma unroll
    for (int i = 0; i < per; i++) s += g_cnt[cb][base + i];
    __shared__ int sh[1024];
    sh[t] = s;
    __syncthreads();
    for (int off = 1; off < 1024; off <<= 1) {
        int v = (t >= off) ? sh[t - off] : 0;
        __syncthreads();
        sh[t] += v;
        __syncthreads();
    }
    int excl = (t == 0) ? 0 : sh[t - 1];
#pragma unroll
    for (int i = 0; i < per; i++) {
        g_start[cb][base + i] = excl;
        excl += g_cnt[cb][base + i];
    }
    if (t == 1023) g_start[cb][GC] = sh[1023];
}

// ---------- scatter (both clouds) ----------
__global__ void scatter_kernel(const float* __restrict__ P1, const float* __restrict__ P2,
                               int N, int M) {
    int i = blockIdx.x * blockDim.x + threadIdx.x;
    const int tot1 = NB * N;
    if (i >= tot1 + NB * M) return;
    int cb, slot;
    const float* p;
    if (i < tot1) { cb = i / N; slot = i % N; p = P1 + (size_t)i * 3; }
    else { int j = i - tot1; cb = NB + j / M; slot = j % M; p = P2 + (size_t)j * 3; }
    float x = p[0], y = p[1], z = p[2];
    int pos = g_start[cb][g_cid[cb][slot]] + g_rnk[cb][slot];
    g_pts[cb][pos] = make_float4(x, y, z, 0.5f * (x * x + y * y + z * z));
}

// ---------- thread-per-query exact NN search + per-block deterministic sum ----------
// Box rows (z,y) are CONTIGUOUS ranges in the sorted array: [cs[rowb+x0], cs[rowb+x1+1]).
// t = h_p - q.p per candidate; d^2 = 2*(tmin + g_q). Unscanned points >= R*h away.
__global__ __launch_bounds__(256) void search_kernel(int N, int M, float inv0, float inv1) {
    const int i = blockIdx.x * blockDim.x + threadIdx.x;
    const int tot1 = NB * N;
    const int total = tot1 + NB * M;

    float contrib = 0.f;
    if (i < total) {
        int qcb, rcb;
        float w;
        if (i < tot1) { qcb = i / N; rcb = NB + qcb; w = inv1; }
        else { int j = i - tot1; qcb = NB + j / M; rcb = qcb - NB; w = inv0; }
        const int slot = (i < tot1) ? (i % N) : ((i - tot1) % M);

        float mnx, mny, mnz, inv, h;
        load_grid(mnx, mny, mnz, inv, h);

        const float4 q = g_pts[qcb][slot];  // sorted order -> warp-coherent cells
        const float nqx = -q.x, nqy = -q.y, nqz = -q.z, gq = q.w;
        const int cx = cellof(q.x, mnx, inv);
        const int cy = cellof(q.y, mny, inv);
        const int cz = cellof(q.z, mnz, inv);

        const float4* __restrict__ pts = g_pts[rcb];
        const int* __restrict__ cs = g_start[rcb];

        float tmin = FLT_MAX;
        float best;
        int R = 1;
        for (;; R++) {
            const int z0 = max(cz - R, 0), z1 = min(cz + R, G - 1);
            const int y0 = max(cy - R, 0), y1 = min(cy + R, G - 1);
            const int x0 = max(cx - R, 0), x1 = min(cx + R, G - 1);
            for (int z = z0; z <= z1; z++) {
                for (int y = y0; y <= y1; y++) {
                    const int rowb = (z * G + y) * G;
                    const int s = cs[rowb + x0];
                    const int e = cs[rowb + x1 + 1];
                    for (int k = s; k < e; k++) {
                        float4 p = pts[k];
                        float t = fmaf(p.x, nqx, fmaf(p.y, nqy, fmaf(p.z, nqz, p.w)));
                        tmin = fminf(tmin, t);
                    }
                }
            }
            best = fmaxf(0.f, 2.f * (tmin + gq));
            const float bd = (float)R * h;
            if (best <= bd * bd || R >= G) break;
        }
        contrib = sqrtf(best) * w;
    }

    // Deterministic per-block reduction (block membership is fixed).
    float acc = contrib;
#pragma unroll
    for (int off = 16; off > 0; off >>= 1)
        acc += __shfl_down_sync(0xFFFFFFFFu, acc, off);
    __shared__ float s[8];
    if ((threadIdx.x & 31) == 0) s[threadIdx.x >> 5] = acc;
    __syncthreads();
    if (threadIdx.x < 8) {
        float v = s[threadIdx.x];
#pragma unroll
        for (int off = 4; off > 0; off >>= 1)
            v += __shfl_down_sync(0xFFu, v, off);
        if (threadIdx.x == 0) g_part[blockIdx.x] = v;
    }
}

// ---------- final reduce over 256 block partials ----------
__global__ void final_kernel(float* __restrict__ out, int nPart) {
    float v = (threadIdx.x < nPart) ? g_part[threadIdx.x] : 0.f;
    __shared__ float s[256];
    s[threadIdx.x] = v;
    __syncthreads();
    for (int st = 128; st > 0; st >>= 1) {
        if (threadIdx.x < st) s[threadIdx.x] += s[threadIdx.x + st];
        __syncthreads();
    }
    if (threadIdx.x == 0) out[0] = s[0];
}

extern "C" void kernel_launch(void* const* d_in, const int* in_sizes, int n_in,
                              void* d_out, int out_size) {
    const float* in1 = (const float*)d_in[0];  // [B, N, 3] cloud1
    const float* in2 = (const float*)d_in[1];  // [B, M, 3] cloud2
    const int K = 3;
    const int N = in_sizes[0] / (NB * K);
    const int M = in_sizes[1] / (NB * K);
    const int totPts = NB * (N + M);
    const int nBlocks = (totPts + 255) / 256;  // 256 for the 8192/8192 shape

    bbox_kernel<<<128, 256>>>(in1, in2, NB * N, NB * M);
    count_kernel<<<nBlocks, 256>>>(in1, in2, N, M);
    scan_kernel<<<NCB, 1024>>>();
    scatter_kernel<<<nBlocks, 256>>>(in1, in2, N, M);
    search_kernel<<<nBlocks, 256>>>(N, M, 1.f / (float)(NB * M), 1.f / (float)(NB * N));
    final_kernel<<<1, 256>>>((float*)d_out, nBlocks);
}